// round 14
// baseline (speedup 1.0000x reference)
#include <cuda_runtime.h>

// spixel_upsample2d: out[b, 4h+a, 4w+d] = sum_{c<2, ky<3, kx<3}
//     cv[b, c, h+ky-1, w+kx-1] * sp[b, c*9 + ky*3+kx, 4h+a, 4w+d]
// cv: (4,2,128,256) fp32 (1 MB, L2-resident)  sp: (4,18,512,1024) fp32 (151 MB streamed)
// out: (4,1,512,1024) fp32 (8.4 MB)
//
// R13: best of both measured axes.
//  - Schedule/body from R8 (best isolated launch: 25.98us, DRAM 77.3%):
//    256-thr CTAs, grid 2048 (one output row each), occ-2 reg budget, all 18
//    sp loads staged up-front for full per-thread MLP.
//  - Streaming hints from R12 (best replay behavior): __ldcs on sp, __stcs on
//    out collapse the graph-replay wall-vs-ncu gap from ~3.3us to ~0.5us by
//    keeping L2 free of dirty/stale residue between back-to-back replays.

#define BB 4
#define CC 2
#define HH 128
#define WW 256
#define H4 512
#define W4 1024

__global__ __launch_bounds__(256, 2)
void spixel_up_kernel(const float* __restrict__ cv,
                      const float* __restrict__ sp,
                      float* __restrict__ out) {
    const int w  = threadIdx.x;            // coarse column 0..255
    const int by = blockIdx.x;             // 0..2047 = b*512 + y
    const int y  = by & (H4 - 1);          // output row
    const int b  = by >> 9;                // batch
    const int h  = y >> 2;                 // coarse row

    const size_t ch_stride4 = (size_t)H4 * W4 / 4;   // float4 per sp channel
    const float4* __restrict__ spb =
        reinterpret_cast<const float4*>(sp) +
        (size_t)b * 18 * ch_stride4 + (size_t)y * (W4 / 4) + w;

    // ---- issue all 18 independent streaming LDG.128 first (full MLP) ----
    float4 s[18];
#pragma unroll
    for (int j = 0; j < 18; j++)
        s[j] = __ldcs(&spb[(size_t)j * ch_stride4]);   // evict-first: no reuse

    // ---- 18 patch values (L1/L2-hot; overlaps sp latency) ----
    float p[18];
#pragma unroll
    for (int c = 0; c < CC; c++) {
        const float* __restrict__ xb = cv + ((size_t)(b * CC + c) * HH) * WW;
#pragma unroll
        for (int ky = 0; ky < 3; ky++) {
            const int hh = h + ky - 1;
            const bool hv = (hh >= 0) && (hh < HH);
#pragma unroll
            for (int kx = 0; kx < 3; kx++) {
                const int wwc = w + kx - 1;
                const bool v = hv && (wwc >= 0) && (wwc < WW);
                p[c * 9 + ky * 3 + kx] = v ? __ldg(&xb[(size_t)hh * WW + wwc]) : 0.0f;
            }
        }
    }

    // ---- FMA chain ----
    float4 acc = make_float4(0.f, 0.f, 0.f, 0.f);
#pragma unroll
    for (int j = 0; j < 18; j++) {
        acc.x = fmaf(p[j], s[j].x, acc.x);
        acc.y = fmaf(p[j], s[j].y, acc.y);
        acc.z = fmaf(p[j], s[j].z, acc.z);
        acc.w = fmaf(p[j], s[j].w, acc.w);
    }

    // Streaming store: evict-first keeps the dirty set small so the next
    // graph replay starts against a clean L2.
    __stcs(&reinterpret_cast<float4*>(out)[(size_t)b * H4 * (W4 / 4) +
                                           (size_t)y * (W4 / 4) + w], acc);
}

extern "C" void kernel_launch(void* const* d_in, const int* in_sizes, int n_in,
                              void* d_out, int out_size) {
    // Bind inputs by element count (robust to metadata ordering).
    const int CV_N = BB * CC * HH * WW;          // 262144
    const float* cv = nullptr;
    const float* sp = nullptr;
    for (int i = 0; i < n_in; i++) {
        if (in_sizes[i] == CV_N) cv = (const float*)d_in[i];
        else                     sp = (const float*)d_in[i];
    }
    float* out = (float*)d_out;

    dim3 grid(BB * H4);      // 2048 CTAs: one per (b, output row)
    dim3 block(256);         // one thread per float4 of the row
    spixel_up_kernel<<<grid, block>>>(cv, sp, out);
}